// round 12
// baseline (speedup 1.0000x reference)
#include <cuda_runtime.h>
#include <cuda_fp16.h>
#include <cstdint>

// Problem constants (fixed by dataset): N=50000 nodes, E=1.6M edges, K=128 feat dim.
#define NODE_CAP 50048
#define EDGE_CAP 1700000
#define KDIM 128

// Scratch (no cudaMalloc allowed).
__device__ __align__(16) float  g_bufB[NODE_CAP * KDIM];  // gathered layer-1 (128-dim fp32)
__device__ __align__(16) __half g_h1[NODE_CAP * KDIM];    // layer-1 pre-agg features (fp16), NO sO
__device__ __align__(16) __half g_h2[NODE_CAP * 64];      // layer-2 pre-agg features (fp16), NO sO
__device__ __align__(16) float  g_W2f[KDIM * 64];         // W2 @ Wf
__device__ __align__(16) float  g_c2[64];                 // b2 @ Wf + bf
__device__ int   g_degO[NODE_CAP];
__device__ int   g_degI[NODE_CAP];
__device__ float g_sO[NODE_CAP];
__device__ float g_sI[NODE_CAP];
__device__ int   g_rowptr[NODE_CAP + 1];
__device__ int   g_cursor[NODE_CAP];
__device__ int   g_csr[EDGE_CAP];        // src indices grouped by dst

// ---------------------------------------------------------------------------
// Single-block prefix scan over deg_in -> row_ptr (exclusive) + cursors.
// ---------------------------------------------------------------------------
__global__ void scan_kernel(int n) {
    __shared__ int part[1024];
    int tid = threadIdx.x;
    int CH = (n + 1023) / 1024;
    int beg = tid * CH;
    int sum = 0;
#pragma unroll 4
    for (int i = 0; i < CH; i++) {
        int idx = beg + i;
        if (idx < n) sum += g_degI[idx];
    }
    part[tid] = sum;
    __syncthreads();
    for (int off = 1; off < 1024; off <<= 1) {
        int v = (tid >= off) ? part[tid - off] : 0;
        __syncthreads();
        part[tid] += v;
        __syncthreads();
    }
    int run = (tid == 0) ? 0 : part[tid - 1];
#pragma unroll 4
    for (int i = 0; i < CH; i++) {
        int idx = beg + i;
        if (idx < n) {
            g_rowptr[idx] = run;
            g_cursor[idx] = run;
            run += g_degI[idx];
        }
    }
    if (tid == 1023) g_rowptr[n] = part[1023];
}

// ---------------------------------------------------------------------------
// Fill CSR (all blocks, 2 edges/thread) + fused side jobs in low blocks:
//   blocks [0,32):  W2f = W2 @ Wf  (128x64, one element/thread)
//   block  32:      c2 = b2 @ Wf + bf
//   blocks [33,33+ceil(n/256)): s_I / s_O rsqrt scales
// ---------------------------------------------------------------------------
__global__ void fill_kernel(const int* __restrict__ src, const int* __restrict__ dst,
                            const float* __restrict__ W2, const float* __restrict__ Wf,
                            const float* __restrict__ b2, const float* __restrict__ bf,
                            int E, int n) {
    int b = blockIdx.x;
    int tid = threadIdx.x;

    int i = (b * 256 + tid) * 2;
    if (i < E) {
        int d0 = dst[i], s0 = src[i];
        if (i + 1 < E) {
            int d1 = dst[i + 1], s1 = src[i + 1];
            int p0 = atomicAdd(&g_cursor[d0], 1);
            int p1 = atomicAdd(&g_cursor[d1], 1);
            g_csr[p0] = s0;
            g_csr[p1] = s1;
        } else {
            int p0 = atomicAdd(&g_cursor[d0], 1);
            g_csr[p0] = s0;
        }
    }

    if (b < 32) {                       // W2f
        int idx = b * 256 + tid;        // < 8192 = 128*64
        int r = idx >> 6;
        int c = idx & 63;
        float s = 0.f;
#pragma unroll 8
        for (int k = 0; k < KDIM; k++)
            s += __ldg(&W2[r * KDIM + k]) * __ldg(&Wf[k * 64 + c]);
        g_W2f[idx] = s;
    } else if (b == 32) {               // c2
        if (tid < 64) {
            float s = __ldg(&bf[tid]);
#pragma unroll 8
            for (int k = 0; k < KDIM; k++)
                s += __ldg(&b2[k]) * __ldg(&Wf[k * 64 + tid]);
            g_c2[tid] = s;
        }
    } else {                            // scales
        int idx = (b - 33) * 256 + tid;
        if (idx < n) {
            g_sI[idx] = rsqrtf((float)max(g_degI[idx], 1));
            g_sO[idx] = rsqrtf((float)max(g_degO[idx], 1));
        }
    }
}

// ---------------------------------------------------------------------------
// Pull aggregation, fp16 input, 128-dim rows, s_O[src] applied here (proven
// R9 unroll-2 form):  B[w] = sum_{s in N_in(w)} sO[s] * h1[s]
// ---------------------------------------------------------------------------
__global__ void gather128h_kernel(const uint2* __restrict__ H, float4* __restrict__ Out, int n) {
    int gt = blockIdx.x * blockDim.x + threadIdx.x;
    int w = gt >> 5;
    int l = gt & 31;
    if (w >= n) return;
    int j = g_rowptr[w];
    int end = g_rowptr[w + 1];
    float4 a0 = make_float4(0.f, 0.f, 0.f, 0.f);
    float4 a1 = make_float4(0.f, 0.f, 0.f, 0.f);
    for (; j + 2 <= end; j += 2) {
        int s0 = __ldg(&g_csr[j]);
        int s1 = __ldg(&g_csr[j + 1]);
        float c0 = __ldg(&g_sO[s0]);
        float c1 = __ldg(&g_sO[s1]);
        uint2 q0 = __ldg(&H[s0 * 32 + l]);
        uint2 q1 = __ldg(&H[s1 * 32 + l]);
        float2 x0 = __half22float2(*(__half2*)&q0.x);
        float2 y0 = __half22float2(*(__half2*)&q0.y);
        float2 x1 = __half22float2(*(__half2*)&q1.x);
        float2 y1 = __half22float2(*(__half2*)&q1.y);
        a0.x += c0 * x0.x; a0.y += c0 * x0.y; a0.z += c0 * y0.x; a0.w += c0 * y0.y;
        a1.x += c1 * x1.x; a1.y += c1 * x1.y; a1.z += c1 * y1.x; a1.w += c1 * y1.y;
    }
    if (j < end) {
        int s0 = __ldg(&g_csr[j]);
        float c0 = __ldg(&g_sO[s0]);
        uint2 q0 = __ldg(&H[s0 * 32 + l]);
        float2 x0 = __half22float2(*(__half2*)&q0.x);
        float2 y0 = __half22float2(*(__half2*)&q0.y);
        a0.x += c0 * x0.x; a0.y += c0 * x0.y; a0.z += c0 * y0.x; a0.w += c0 * y0.y;
    }
    Out[w * 32 + l] = make_float4(a0.x + a1.x, a0.y + a1.y, a0.z + a1.z, a0.w + a1.w);
}

// ---------------------------------------------------------------------------
// Pull aggregation, fp16 input, 64-dim rows, s_O[src] applied, final epilogue
// fused:  out[w][c] = (sum sO[s]*h2[s][c]) * sI[w] + c2[c]
// ---------------------------------------------------------------------------
__global__ void gather64h_kernel(const __half2* __restrict__ H, float2* __restrict__ Out, int n) {
    int gt = blockIdx.x * blockDim.x + threadIdx.x;
    int w = gt >> 5;
    int l = gt & 31;
    if (w >= n) return;
    int j = g_rowptr[w];
    int end = g_rowptr[w + 1];
    float2 a0 = make_float2(0.f, 0.f);
    float2 a1 = make_float2(0.f, 0.f);
    for (; j + 2 <= end; j += 2) {
        int s0 = __ldg(&g_csr[j]);
        int s1 = __ldg(&g_csr[j + 1]);
        float c0 = __ldg(&g_sO[s0]);
        float c1 = __ldg(&g_sO[s1]);
        float2 f0 = __half22float2(__ldg(&H[s0 * 32 + l]));
        float2 f1 = __half22float2(__ldg(&H[s1 * 32 + l]));
        a0.x += c0 * f0.x; a0.y += c0 * f0.y;
        a1.x += c1 * f1.x; a1.y += c1 * f1.y;
    }
    if (j < end) {
        int s0 = __ldg(&g_csr[j]);
        float c0 = __ldg(&g_sO[s0]);
        float2 f0 = __half22float2(__ldg(&H[s0 * 32 + l]));
        a0.x += c0 * f0.x; a0.y += c0 * f0.y;
    }
    float si = g_sI[w];
    float2 b = *(const float2*)&g_c2[l * 2];
    Out[w * 32 + l] = make_float2((a0.x + a1.x) * si + b.x, (a0.y + a1.y) * si + b.y);
}

// ---------------------------------------------------------------------------
// fp32 register-tiled GEMM, N-split for occupancy:
//   Ch[M, NFULL] (fp16) = f(A[M,128]) @ W[128, NFULL]
// Each block computes NSUB=64 columns starting at blockIdx.y*64.
// smem = W-half (32KB) + A-tile (32KB) = 64KB -> 3 CTAs/SM (vs 2 at 96KB).
//   MODE 0: a = A[r][k]                           (plain; sO moved to gather)
//   MODE 1: a = max(A[r][k]*s_in[r] + bias[k], 0) (layer-1 epilogue fused)
// DEG=true: blockIdx.y==0 blocks also count edge degrees with fire-and-forget
// REDs (hidden under the GEMM).
// ---------------------------------------------------------------------------
template <int NFULL, int MODE, bool DEG>
__global__ void gemm_kernel(const float* __restrict__ A_src, const float* __restrict__ W,
                            const float* __restrict__ bias_in,
                            __half* __restrict__ Outh, int M,
                            const int* __restrict__ src, const int* __restrict__ dst, int E) {
    constexpr int BM = 64;
    constexpr int NSUB = 64;
    extern __shared__ float smem[];
    float* Ws = smem;               // KDIM * NSUB
    float* As = smem + KDIM * NSUB; // BM * KDIM

    int tid = threadIdx.x;
    int m0 = blockIdx.x * BM;
    int n0 = blockIdx.y * NSUB;

    if (DEG && blockIdx.y == 0) {
        int gid = blockIdx.x * blockDim.x + tid;
        int stride = (gridDim.x) * blockDim.x;
        for (int e = gid; e < E; e += stride) {
            atomicAdd(&g_degO[src[e]], 1);   // RED: no return value used
            atomicAdd(&g_degI[dst[e]], 1);
        }
    }

    // Stage W columns [n0, n0+NSUB): float4 loads
    for (int i = tid * 4; i < KDIM * NSUB; i += 256 * 4) {
        int k = i / NSUB;
        int c = i % NSUB;
        *(float4*)&Ws[k * NSUB + c] = *(const float4*)&W[k * NFULL + n0 + c];
    }

    // Stage A tile with fused prologue transform
    for (int i = tid; i < BM * KDIM / 4; i += 256) {
        int r = i >> 5;
        int kc = (i & 31) * 4;
        int gr = m0 + r;
        float4 v = make_float4(0.f, 0.f, 0.f, 0.f);
        if (gr < M) {
            v = *(const float4*)&A_src[gr * KDIM + kc];
            if (MODE == 1) {
                float si = g_sI[gr];
                float4 b = *(const float4*)&bias_in[kc];
                v.x = fmaxf(v.x * si + b.x, 0.f);
                v.y = fmaxf(v.y * si + b.y, 0.f);
                v.z = fmaxf(v.z * si + b.z, 0.f);
                v.w = fmaxf(v.w * si + b.w, 0.f);
            }
        }
        *(float4*)&As[r * KDIM + kc] = v;
    }
    __syncthreads();

    constexpr int CT = NSUB / 4;     // 16
    constexpr int RT = 256 / CT;     // 16
    constexpr int RPT = BM / RT;     // 4
    int ct = tid % CT;
    int rt = tid / CT;
    int c0 = ct * 4;
    int r0 = rt * RPT;

    float4 acc[RPT];
#pragma unroll
    for (int i = 0; i < RPT; i++) acc[i] = make_float4(0.f, 0.f, 0.f, 0.f);

#pragma unroll 4
    for (int k = 0; k < KDIM; k++) {
        float4 b = *(const float4*)&Ws[k * NSUB + c0];
#pragma unroll
        for (int i = 0; i < RPT; i++) {
            float a = As[(r0 + i) * KDIM + k];
            acc[i].x += a * b.x;
            acc[i].y += a * b.y;
            acc[i].z += a * b.z;
            acc[i].w += a * b.w;
        }
    }

#pragma unroll
    for (int i = 0; i < RPT; i++) {
        int gr = m0 + r0 + i;
        if (gr < M) {
            float4 o = acc[i];
            __half2 lo = __floats2half2_rn(o.x, o.y);
            __half2 hi = __floats2half2_rn(o.z, o.w);
            uint2 u;
            u.x = *(unsigned*)&lo;
            u.y = *(unsigned*)&hi;
            *(uint2*)&Outh[gr * NFULL + n0 + c0] = u;
        }
    }
}

// ---------------------------------------------------------------------------
extern "C" void kernel_launch(void* const* d_in, const int* in_sizes, int n_in,
                              void* d_out, int out_size) {
    const float* X  = (const float*)d_in[0];
    const int* src  = (const int*)d_in[1];
    const int* dst  = (const int*)d_in[2];
    const float* W1 = (const float*)d_in[3];
    const float* b1 = (const float*)d_in[4];
    const float* W2 = (const float*)d_in[5];
    const float* b2 = (const float*)d_in[6];
    const float* Wf = (const float*)d_in[7];
    const float* bf = (const float*)d_in[8];
    float* out = (float*)d_out;

    int n = in_sizes[0] / KDIM;   // 50000
    int E = in_sizes[1];          // 1600000

    void *pB_, *pH1_, *pH2_, *pW2f_, *pDO_, *pDI_;
    cudaGetSymbolAddress(&pB_, g_bufB);
    cudaGetSymbolAddress(&pH1_, g_h1);
    cudaGetSymbolAddress(&pH2_, g_h2);
    cudaGetSymbolAddress(&pW2f_, g_W2f);
    cudaGetSymbolAddress(&pDO_, g_degO);
    cudaGetSymbolAddress(&pDI_, g_degI);

    const int smem64 = (KDIM * 64 + 64 * KDIM) * sizeof(float); // 64KB
    cudaFuncSetAttribute(gemm_kernel<128, 0, true>, cudaFuncAttributeMaxDynamicSharedMemorySize, smem64);
    cudaFuncSetAttribute(gemm_kernel<64, 1, false>, cudaFuncAttributeMaxDynamicSharedMemorySize, smem64);

    int gemm_blocks  = (n + 63) / 64;                 // 782
    int agg_blocks   = (n * 32 + 255) / 256;          // 6250
    int fill_blocks  = ((E + 1) / 2 + 255) / 256;     // 3125 (>= 229 side-job blocks)

    // 1. zero degree counters
    cudaMemsetAsync(pDO_, 0, n * sizeof(int));
    cudaMemsetAsync(pDI_, 0, n * sizeof(int));

    // 2. layer-1 GEMM (plain X@W1 -> fp16), N split in 2, degree atomics hidden
    {
        dim3 grid(gemm_blocks, 2);
        gemm_kernel<128, 0, true><<<grid, 256, smem64>>>(
            X, W1, nullptr, (__half*)pH1_, n, src, dst, E);
    }

    // 3. rowptr scan, then CSR fill (+ fused W2f/c2/scales side jobs)
    scan_kernel<<<1, 1024>>>(n);
    fill_kernel<<<fill_blocks, 256>>>(src, dst, W2, Wf, b2, bf, E, n);

    // 4. aggregate layer 1 (applies sO[src]): B = sum sO[s]*h1[s]
    gather128h_kernel<<<agg_blocks, 256>>>((const uint2*)pH1_, (float4*)pB_, n);

    // 5. layer-2 GEMM: h2 = relu(B*sI + b1) @ (W2@Wf) -> fp16
    gemm_kernel<64, 1, false><<<dim3(gemm_blocks, 1), 256, smem64>>>(
        (const float*)pB_, (const float*)pW2f_, b1, (__half*)pH2_, n,
        nullptr, nullptr, 0);

    // 6. aggregate layer 2 (applies sO[src]) + final epilogue -> out
    gather64h_kernel<<<agg_blocks, 256>>>((const __half2*)pH2_, (float2*)out, n);
}

// round 14
// speedup vs baseline: 1.4873x; 1.4873x over previous
#include <cuda_runtime.h>
#include <cuda_fp16.h>
#include <cstdint>

// Problem constants (fixed by dataset): N=50000 nodes, E=1.6M edges, K=128 feat dim.
#define NODE_CAP 50048
#define EDGE_CAP 1700000
#define KDIM 128

// Scratch (no cudaMalloc allowed).
__device__ __align__(16) float  g_bufB[NODE_CAP * KDIM];  // gathered layer-1 (128-dim fp32)
__device__ __align__(16) __half g_h1[NODE_CAP * KDIM];    // layer-1 pre-agg features (fp16), NO sO
__device__ __align__(16) __half g_h2[NODE_CAP * 64];      // layer-2 pre-agg features (fp16), NO sO
__device__ __align__(16) float  g_W2f[KDIM * 64];         // W2 @ Wf
__device__ __align__(16) float  g_c2[64];                 // b2 @ Wf + bf
__device__ int   g_degO[NODE_CAP];
__device__ int   g_degI[NODE_CAP];
__device__ float g_sO[NODE_CAP];
__device__ float g_sI[NODE_CAP];
__device__ int   g_rowptr[NODE_CAP + 1];
__device__ int   g_cursor[NODE_CAP];
__device__ int   g_csr[EDGE_CAP];        // src indices grouped by dst

// ---------------------------------------------------------------------------
// Single-block prefix scan over deg_in -> row_ptr (exclusive) + cursors.
// ---------------------------------------------------------------------------
__global__ void scan_kernel(int n) {
    __shared__ int part[1024];
    int tid = threadIdx.x;
    int CH = (n + 1023) / 1024;
    int beg = tid * CH;
    int sum = 0;
#pragma unroll 4
    for (int i = 0; i < CH; i++) {
        int idx = beg + i;
        if (idx < n) sum += g_degI[idx];
    }
    part[tid] = sum;
    __syncthreads();
    for (int off = 1; off < 1024; off <<= 1) {
        int v = (tid >= off) ? part[tid - off] : 0;
        __syncthreads();
        part[tid] += v;
        __syncthreads();
    }
    int run = (tid == 0) ? 0 : part[tid - 1];
#pragma unroll 4
    for (int i = 0; i < CH; i++) {
        int idx = beg + i;
        if (idx < n) {
            g_rowptr[idx] = run;
            g_cursor[idx] = run;
            run += g_degI[idx];
        }
    }
    if (tid == 1023) g_rowptr[n] = part[1023];
}

// ---------------------------------------------------------------------------
// Fill CSR (all blocks, 2 edges/thread) + fused side jobs in low blocks:
//   blocks [0,32):  W2f = W2 @ Wf  (128x64, one element/thread)
//   block  32:      c2 = b2 @ Wf + bf
//   blocks [33,33+ceil(n/256)): s_I / s_O rsqrt scales
// ---------------------------------------------------------------------------
__global__ void fill_kernel(const int* __restrict__ src, const int* __restrict__ dst,
                            const float* __restrict__ W2, const float* __restrict__ Wf,
                            const float* __restrict__ b2, const float* __restrict__ bf,
                            int E, int n) {
    int b = blockIdx.x;
    int tid = threadIdx.x;

    int i = (b * 256 + tid) * 2;
    if (i < E) {
        int d0 = dst[i], s0 = src[i];
        if (i + 1 < E) {
            int d1 = dst[i + 1], s1 = src[i + 1];
            int p0 = atomicAdd(&g_cursor[d0], 1);
            int p1 = atomicAdd(&g_cursor[d1], 1);
            g_csr[p0] = s0;
            g_csr[p1] = s1;
        } else {
            int p0 = atomicAdd(&g_cursor[d0], 1);
            g_csr[p0] = s0;
        }
    }

    if (b < 32) {                       // W2f
        int idx = b * 256 + tid;        // < 8192 = 128*64
        int r = idx >> 6;
        int c = idx & 63;
        float s = 0.f;
#pragma unroll 8
        for (int k = 0; k < KDIM; k++)
            s += __ldg(&W2[r * KDIM + k]) * __ldg(&Wf[k * 64 + c]);
        g_W2f[idx] = s;
    } else if (b == 32) {               // c2
        if (tid < 64) {
            float s = __ldg(&bf[tid]);
#pragma unroll 8
            for (int k = 0; k < KDIM; k++)
                s += __ldg(&b2[k]) * __ldg(&Wf[k * 64 + tid]);
            g_c2[tid] = s;
        }
    } else {                            // scales
        int idx = (b - 33) * 256 + tid;
        if (idx < n) {
            g_sI[idx] = rsqrtf((float)max(g_degI[idx], 1));
            g_sO[idx] = rsqrtf((float)max(g_degO[idx], 1));
        }
    }
}

// ---------------------------------------------------------------------------
// Pull aggregation, fp16 input, 128-dim rows, with s_O[src] applied here:
//   B[w] = sum_{s in N_in(w)} sO[s] * h1[s]
// Warp per dst node; lane l owns halfs [4l,4l+4). Uniform-address csr/sO loads
// (warp broadcast), unroll-2 for MLP. fp32 accumulate.
// ---------------------------------------------------------------------------
__global__ void gather128h_kernel(const uint2* __restrict__ H, float4* __restrict__ Out, int n) {
    int gt = blockIdx.x * blockDim.x + threadIdx.x;
    int w = gt >> 5;
    int l = gt & 31;
    if (w >= n) return;
    int j = g_rowptr[w];
    int end = g_rowptr[w + 1];
    float4 a0 = make_float4(0.f, 0.f, 0.f, 0.f);
    float4 a1 = make_float4(0.f, 0.f, 0.f, 0.f);
    for (; j + 2 <= end; j += 2) {
        int s0 = __ldg(&g_csr[j]);
        int s1 = __ldg(&g_csr[j + 1]);
        float c0 = __ldg(&g_sO[s0]);
        float c1 = __ldg(&g_sO[s1]);
        uint2 q0 = __ldg(&H[s0 * 32 + l]);
        uint2 q1 = __ldg(&H[s1 * 32 + l]);
        float2 x0 = __half22float2(*(__half2*)&q0.x);
        float2 y0 = __half22float2(*(__half2*)&q0.y);
        float2 x1 = __half22float2(*(__half2*)&q1.x);
        float2 y1 = __half22float2(*(__half2*)&q1.y);
        a0.x += c0 * x0.x; a0.y += c0 * x0.y; a0.z += c0 * y0.x; a0.w += c0 * y0.y;
        a1.x += c1 * x1.x; a1.y += c1 * x1.y; a1.z += c1 * y1.x; a1.w += c1 * y1.y;
    }
    if (j < end) {
        int s0 = __ldg(&g_csr[j]);
        float c0 = __ldg(&g_sO[s0]);
        uint2 q0 = __ldg(&H[s0 * 32 + l]);
        float2 x0 = __half22float2(*(__half2*)&q0.x);
        float2 y0 = __half22float2(*(__half2*)&q0.y);
        a0.x += c0 * x0.x; a0.y += c0 * x0.y; a0.z += c0 * y0.x; a0.w += c0 * y0.y;
    }
    Out[w * 32 + l] = make_float4(a0.x + a1.x, a0.y + a1.y, a0.z + a1.z, a0.w + a1.w);
}

// ---------------------------------------------------------------------------
// Pull aggregation, fp16 input, 64-dim rows, s_O[src] applied, final epilogue
// fused:  out[w][c] = (sum sO[s]*h2[s][c]) * sI[w] + c2[c]
// ---------------------------------------------------------------------------
__global__ void gather64h_kernel(const __half2* __restrict__ H, float2* __restrict__ Out, int n) {
    int gt = blockIdx.x * blockDim.x + threadIdx.x;
    int w = gt >> 5;
    int l = gt & 31;
    if (w >= n) return;
    int j = g_rowptr[w];
    int end = g_rowptr[w + 1];
    float2 a0 = make_float2(0.f, 0.f);
    float2 a1 = make_float2(0.f, 0.f);
    for (; j + 2 <= end; j += 2) {
        int s0 = __ldg(&g_csr[j]);
        int s1 = __ldg(&g_csr[j + 1]);
        float c0 = __ldg(&g_sO[s0]);
        float c1 = __ldg(&g_sO[s1]);
        float2 f0 = __half22float2(__ldg(&H[s0 * 32 + l]));
        float2 f1 = __half22float2(__ldg(&H[s1 * 32 + l]));
        a0.x += c0 * f0.x; a0.y += c0 * f0.y;
        a1.x += c1 * f1.x; a1.y += c1 * f1.y;
    }
    if (j < end) {
        int s0 = __ldg(&g_csr[j]);
        float c0 = __ldg(&g_sO[s0]);
        float2 f0 = __half22float2(__ldg(&H[s0 * 32 + l]));
        a0.x += c0 * f0.x; a0.y += c0 * f0.y;
    }
    float si = g_sI[w];
    float2 b = *(const float2*)&g_c2[l * 2];
    Out[w * 32 + l] = make_float2((a0.x + a1.x) * si + b.x, (a0.y + a1.y) * si + b.y);
}

// ---------------------------------------------------------------------------
// fp32 register-tiled GEMM (proven config): Ch[M,N] (fp16) = f(A[M,128]) @ W[128,N]
//   MODE 0: a = A[r][k]                           (plain; sO moved to gather)
//   MODE 1: a = max(A[r][k]*s_in[r] + bias[k], 0) (layer-1 epilogue fused)
// DEG=true additionally counts edge degrees with fire-and-forget REDs at the
// top (no result -> no scoreboard stall; latency hidden under the GEMM).
// BM=64 rows/block, 256 threads, W + A-tile staged in dynamic smem.
// ---------------------------------------------------------------------------
template <int N, int MODE, bool DEG>
__global__ void gemm_kernel(const float* __restrict__ A_src, const float* __restrict__ W,
                            const float* __restrict__ bias_in,
                            __half* __restrict__ Outh, int M,
                            const int* __restrict__ src, const int* __restrict__ dst, int E) {
    constexpr int BM = 64;
    extern __shared__ float smem[];
    float* Ws = smem;            // K * N
    float* As = smem + KDIM * N; // BM * K

    int tid = threadIdx.x;
    int m0 = blockIdx.x * BM;

    if (DEG) {
        int gid = blockIdx.x * blockDim.x + tid;
        int stride = gridDim.x * blockDim.x;
        for (int e = gid; e < E; e += stride) {
            atomicAdd(&g_degO[src[e]], 1);   // RED: no return value used
            atomicAdd(&g_degI[dst[e]], 1);
        }
    }

    for (int i = tid * 4; i < KDIM * N; i += 256 * 4) {
        *(float4*)&Ws[i] = *(const float4*)&W[i];
    }

    for (int i = tid; i < BM * KDIM / 4; i += 256) {
        int r = i >> 5;
        int kc = (i & 31) * 4;
        int gr = m0 + r;
        float4 v = make_float4(0.f, 0.f, 0.f, 0.f);
        if (gr < M) {
            v = *(const float4*)&A_src[gr * KDIM + kc];
            if (MODE == 1) {
                float si = g_sI[gr];
                float4 b = *(const float4*)&bias_in[kc];
                v.x = fmaxf(v.x * si + b.x, 0.f);
                v.y = fmaxf(v.y * si + b.y, 0.f);
                v.z = fmaxf(v.z * si + b.z, 0.f);
                v.w = fmaxf(v.w * si + b.w, 0.f);
            }
        }
        *(float4*)&As[r * KDIM + kc] = v;
    }
    __syncthreads();

    constexpr int CT = N / 4;        // 32 (N=128) or 16 (N=64)
    constexpr int RT = 256 / CT;     // 8 or 16
    constexpr int RPT = BM / RT;     // 8 or 4
    int ct = tid % CT;
    int rt = tid / CT;
    int c0 = ct * 4;
    int r0 = rt * RPT;

    float4 acc[RPT];
#pragma unroll
    for (int i = 0; i < RPT; i++) acc[i] = make_float4(0.f, 0.f, 0.f, 0.f);

#pragma unroll 4
    for (int k = 0; k < KDIM; k++) {
        float4 b = *(const float4*)&Ws[k * N + c0];
#pragma unroll
        for (int i = 0; i < RPT; i++) {
            float a = As[(r0 + i) * KDIM + k];
            acc[i].x += a * b.x;
            acc[i].y += a * b.y;
            acc[i].z += a * b.z;
            acc[i].w += a * b.w;
        }
    }

#pragma unroll
    for (int i = 0; i < RPT; i++) {
        int gr = m0 + r0 + i;
        if (gr < M) {
            float4 o = acc[i];
            __half2 lo = __floats2half2_rn(o.x, o.y);
            __half2 hi = __floats2half2_rn(o.z, o.w);
            uint2 u;
            u.x = *(unsigned*)&lo;
            u.y = *(unsigned*)&hi;
            *(uint2*)&Outh[gr * N + c0] = u;
        }
    }
}

// ---------------------------------------------------------------------------
extern "C" void kernel_launch(void* const* d_in, const int* in_sizes, int n_in,
                              void* d_out, int out_size) {
    const float* X  = (const float*)d_in[0];
    const int* src  = (const int*)d_in[1];
    const int* dst  = (const int*)d_in[2];
    const float* W1 = (const float*)d_in[3];
    const float* b1 = (const float*)d_in[4];
    const float* W2 = (const float*)d_in[5];
    const float* b2 = (const float*)d_in[6];
    const float* Wf = (const float*)d_in[7];
    const float* bf = (const float*)d_in[8];
    float* out = (float*)d_out;

    int n = in_sizes[0] / KDIM;   // 50000
    int E = in_sizes[1];          // 1600000

    void *pB_, *pH1_, *pH2_, *pW2f_, *pDO_, *pDI_;
    cudaGetSymbolAddress(&pB_, g_bufB);
    cudaGetSymbolAddress(&pH1_, g_h1);
    cudaGetSymbolAddress(&pH2_, g_h2);
    cudaGetSymbolAddress(&pW2f_, g_W2f);
    cudaGetSymbolAddress(&pDO_, g_degO);
    cudaGetSymbolAddress(&pDI_, g_degI);

    const int smem128 = (KDIM * 128 + 64 * KDIM) * sizeof(float); // 96KB
    const int smem64  = (KDIM * 64  + 64 * KDIM) * sizeof(float); // 64KB
    cudaFuncSetAttribute(gemm_kernel<128, 0, true>, cudaFuncAttributeMaxDynamicSharedMemorySize, smem128);
    cudaFuncSetAttribute(gemm_kernel<64, 1, false>, cudaFuncAttributeMaxDynamicSharedMemorySize, smem64);

    int gemm_blocks  = (n + 63) / 64;                 // 782
    int agg_blocks   = (n * 32 + 255) / 256;          // 6250
    int fill_blocks  = ((E + 1) / 2 + 255) / 256;     // 3125 (>= 229 side-job blocks)

    // 1. zero degree counters
    cudaMemsetAsync(pDO_, 0, n * sizeof(int));
    cudaMemsetAsync(pDI_, 0, n * sizeof(int));

    // 2. layer-1 GEMM (plain X@W1 -> fp16) with degree atomics hidden inside
    gemm_kernel<128, 0, true><<<gemm_blocks, 256, smem128>>>(
        X, W1, nullptr, (__half*)pH1_, n, src, dst, E);

    // 3. rowptr scan, then CSR fill (+ fused W2f/c2/scales side jobs)
    scan_kernel<<<1, 1024>>>(n);
    fill_kernel<<<fill_blocks, 256>>>(src, dst, W2, Wf, b2, bf, E, n);

    // 4. aggregate layer 1 (applies sO[src]): B = sum sO[s]*h1[s]
    gather128h_kernel<<<agg_blocks, 256>>>((const uint2*)pH1_, (float4*)pB_, n);

    // 5. layer-2 GEMM: h2 = relu(B*sI + b1) @ (W2@Wf) -> fp16
    gemm_kernel<64, 1, false><<<gemm_blocks, 256, smem64>>>(
        (const float*)pB_, (const float*)pW2f_, b1, (__half*)pH2_, n,
        nullptr, nullptr, 0);

    // 6. aggregate layer 2 (applies sO[src]) + final epilogue -> out
    gather64h_kernel<<<agg_blocks, 256>>>((const __half2*)pH2_, (float2*)out, n);
}